// round 9
// baseline (speedup 1.0000x reference)
#include <cuda_runtime.h>
#include <cuda_bf16.h>
#include <cstdint>

// Problem constants
#define BB 8
#define HH 768
#define LL 4096
#define N2 4096          // complex FFT size (= N/2, N = 8192)
#define LOGN2 12
#define KF_STRIDE 4100   // 4097 used, padded

#define PI_F 3.14159265358979323846f

// Scratch (device globals: allocation APIs are forbidden)
__device__ __nv_bfloat16 g_yh[(size_t)BB * HH * LL];   // gelu(y) hi, ~50 MB
__device__ __nv_bfloat16 g_yl[(size_t)BB * HH * LL];   // gelu(y) lo, ~50 MB
__device__ __nv_bfloat16 g_wh[(size_t)2 * HH * HH];    // W hi
__device__ __nv_bfloat16 g_wl[(size_t)2 * HH * HH];    // W lo
__device__ float2 g_kf[(size_t)HH * KF_STRIDE];        // kernel spectrum, ~25 MB

// ---------------------------------------------------------------------------
// complex helpers
__device__ __forceinline__ float2 cmul(float2 a, float2 b) {
    return make_float2(a.x * b.x - a.y * b.y, a.x * b.y + a.y * b.x);
}
__device__ __forceinline__ float2 cmulc(float2 a, float2 b) {  // a * conj(b)
    return make_float2(a.x * b.x + a.y * b.y, a.y * b.x - a.x * b.y);
}

__device__ __forceinline__ float gelu_exact(float x) {
    return 0.5f * x * (1.0f + erff(x * 0.70710678118654752f));
}

// ---------------------------------------------------------------------------
// Stockham radix-2 FFT of 4096 complex points in shared memory.
template <bool INV>
__device__ void fft4096(float2* bufA, float2* bufB, const float2* tw, int tid) {
    float2* src = bufA;
    float2* dst = bufB;
#pragma unroll 1
    for (int stage = 0; stage < LOGN2; ++stage) {
        __syncthreads();
        const int s = 1 << stage;
#pragma unroll
        for (int it = 0; it < 4; ++it) {
            int i = tid + it * 512;          // 0..2047  (i = p*s + q)
            int p = i >> stage;
            int q = i & (s - 1);
            float2 w = tw[p << stage];
            if (INV) w.y = -w.y;
            float2 a  = src[i];
            float2 b  = src[i + 2048];
            float2 sum = make_float2(a.x + b.x, a.y + b.y);
            float2 dif = make_float2(a.x - b.x, a.y - b.y);
            int od = q + s * 2 * p;
            dst[od]     = sum;
            dst[od + s] = cmul(dif, w);
        }
        float2* t = src; src = dst; dst = t;
    }
    __syncthreads();
}

__device__ __forceinline__ void build_twiddles(float2* tw, int tid) {
    for (int i = tid; i < 2048; i += 512) {
        float s, c;
        __sincosf(-(2.0f * PI_F / (float)N2) * (float)i, &s, &c);
        tw[i] = make_float2(c, s);
    }
}

// ---------------------------------------------------------------------------
// Kernel 1: spectrum of conv kernel k (768 rows).
__global__ void kf_kernel(const float* __restrict__ kin) {
    extern __shared__ float2 sm[];
    float2* A  = sm;
    float2* Bb = sm + N2;
    float2* tw = sm + 2 * N2;
    const int h   = blockIdx.x;
    const int tid = threadIdx.x;

    build_twiddles(tw, tid);

    const float2* kr = (const float2*)(kin + (size_t)h * LL);
#pragma unroll
    for (int it = 0; it < 4; ++it) {
        int n = tid + it * 512;
        A[n] = kr[n];
    }
#pragma unroll
    for (int it = 4; it < 8; ++it) {
        int n = tid + it * 512;
        A[n] = make_float2(0.f, 0.f);
    }

    fft4096<false>(A, Bb, tw, tid);

    float2* kf = g_kf + (size_t)h * KF_STRIDE;
    for (int k = tid; k <= 2048; k += 512) {
        if (k == 0) {
            float2 Z0 = A[0];
            kf[0]    = make_float2(Z0.x + Z0.y, 0.f);
            kf[4096] = make_float2(Z0.x - Z0.y, 0.f);
        } else if (k == 2048) {
            float2 Z = A[2048];
            kf[2048] = make_float2(Z.x, -Z.y);
        } else {
            int kp = N2 - k;
            float2 Zk = A[k], Zp = A[kp];
            float2 Fe = make_float2(0.5f * (Zk.x + Zp.x), 0.5f * (Zk.y - Zp.y));
            float2 Fo = make_float2(0.5f * (Zk.y + Zp.y), 0.5f * (Zp.x - Zk.x));
            float sw, cw;
            __sincosf(-(2.0f * PI_F / 8192.0f) * (float)k, &sw, &cw);
            float2 W = make_float2(cw, sw);
            float2 t = cmul(Fo, W);
            kf[k]  = make_float2(Fe.x + t.x, Fe.y + t.y);
            kf[kp] = make_float2(Fe.x - t.x, -(Fe.y - t.y));
        }
    }
}

// ---------------------------------------------------------------------------
// Kernel 2: per (b,h) row — rfft(u) * Kf -> irfft -> + D*u -> gelu -> split bf16
__global__ void conv_kernel(const float* __restrict__ u, const float* __restrict__ D) {
    extern __shared__ float2 sm[];
    float2* A  = sm;
    float2* Bb = sm + N2;
    float2* tw = sm + 2 * N2;
    const int row = blockIdx.x;          // b*HH + h
    const int tid = threadIdx.x;
    const int hh  = row % HH;

    build_twiddles(tw, tid);

    const float2* u2 = (const float2*)(u + (size_t)row * LL);
    float2 ureg[4];
#pragma unroll
    for (int it = 0; it < 4; ++it) {
        int n = tid + it * 512;
        float2 v = u2[n];
        ureg[it] = v;
        A[n] = v;
    }
#pragma unroll
    for (int it = 4; it < 8; ++it) {
        int n = tid + it * 512;
        A[n] = make_float2(0.f, 0.f);
    }

    fft4096<false>(A, Bb, tw, tid);   // Z in A

    const float2* kf = g_kf + (size_t)hh * KF_STRIDE;
    for (int k = tid; k <= 2048; k += 512) {
        if (k == 0) {
            float2 Z0 = A[0];
            float X0 = Z0.x + Z0.y;
            float X1 = Z0.x - Z0.y;
            float2 K0 = kf[0], K1 = kf[4096];
            float2 Y0 = make_float2(X0 * K0.x, X0 * K0.y);
            float2 Y1 = make_float2(X1 * K1.x, X1 * K1.y);
            float2 Ge = make_float2(0.5f * (Y0.x + Y1.x), 0.5f * (Y0.y - Y1.y));
            float2 Go = make_float2(0.5f * (Y0.x - Y1.x), 0.5f * (Y0.y + Y1.y));
            A[0] = make_float2(Ge.x - Go.y, Ge.y + Go.x);
        } else if (k == 2048) {
            float2 Z = A[2048];
            float2 X = make_float2(Z.x, -Z.y);
            float2 Y = cmul(X, kf[2048]);
            A[2048] = make_float2(Y.x, -Y.y);
        } else {
            int kp = N2 - k;
            float2 Zk = A[k], Zp = A[kp];
            float2 Fe = make_float2(0.5f * (Zk.x + Zp.x), 0.5f * (Zk.y - Zp.y));
            float2 Fo = make_float2(0.5f * (Zk.y + Zp.y), 0.5f * (Zp.x - Zk.x));
            float sw, cw;
            __sincosf(-(2.0f * PI_F / 8192.0f) * (float)k, &sw, &cw);
            float2 W = make_float2(cw, sw);
            float2 t = cmul(Fo, W);
            float2 Xk = make_float2(Fe.x + t.x, Fe.y + t.y);
            float2 Xp = make_float2(Fe.x - t.x, -(Fe.y - t.y));
            float2 Ya = cmul(Xk, kf[k]);
            float2 Yb = cmul(Xp, kf[kp]);
            float2 Ge = make_float2(0.5f * (Ya.x + Yb.x), 0.5f * (Ya.y - Yb.y));
            float2 Am = make_float2(0.5f * (Ya.x - Yb.x), 0.5f * (Ya.y + Yb.y));
            float2 Go = cmulc(Am, W);
            A[k]  = make_float2(Ge.x - Go.y, Ge.y + Go.x);
            A[kp] = make_float2(Ge.x + Go.y, Go.x - Ge.y);
        }
    }

    fft4096<true>(A, Bb, tw, tid);    // z2 in A (unscaled inverse)

    const float Dh  = D[hh];
    const float inv = 1.0f / (float)N2;
    __nv_bfloat16* yh = g_yh + (size_t)row * LL;
    __nv_bfloat16* yl = g_yl + (size_t)row * LL;
#pragma unroll
    for (int it = 0; it < 4; ++it) {
        int n = tid + it * 512;
        float2 z = A[n];
        float y0 = gelu_exact(z.x * inv + Dh * ureg[it].x);
        float y1 = gelu_exact(z.y * inv + Dh * ureg[it].y);
        __nv_bfloat16 h0 = __float2bfloat16(y0);
        __nv_bfloat16 h1 = __float2bfloat16(y1);
        __nv_bfloat16 l0 = __float2bfloat16(y0 - __bfloat162float(h0));
        __nv_bfloat16 l1 = __float2bfloat16(y1 - __bfloat162float(h1));
        __nv_bfloat162 hv; hv.x = h0; hv.y = h1;
        __nv_bfloat162 lv; lv.x = l0; lv.y = l1;
        *(__nv_bfloat162*)(yh + 2 * n) = hv;
        *(__nv_bfloat162*)(yl + 2 * n) = lv;
    }
}

// ---------------------------------------------------------------------------
// Kernel 2b: split W (2H x H fp32) into bf16 hi/lo
__global__ void wsplit_kernel(const float* __restrict__ W) {
    int r = blockIdx.x;
    for (int c = threadIdx.x; c < HH; c += 256) {
        float w = W[(size_t)r * HH + c];
        __nv_bfloat16 hi = __float2bfloat16(w);
        __nv_bfloat16 lo = __float2bfloat16(w - __bfloat162float(hi));
        g_wh[(size_t)r * HH + c] = hi;
        g_wl[(size_t)r * HH + c] = lo;
    }
}

// ---------------------------------------------------------------------------
// Kernel 3: tensor-core GEMM  Z = W(1536x768) @ Y(768x4096) with split-bf16
// (Wh+Wl)(Yh+Yl) ~= Wh*Yh + Wh*Yl + Wl*Yh  (fp32 accum), bias + GLU fused.
// R9: 2-stage smem double-buffer software pipeline (dynamic smem, 2 stages
// x 37888 B), one __syncthreads per K-iter, Y LDG prefetched into regs.
__device__ __forceinline__ void mma_bf16(float* c, const uint32_t* a, const uint32_t* b) {
    asm volatile(
        "mma.sync.aligned.m16n8k16.row.col.f32.bf16.bf16.f32 "
        "{%0,%1,%2,%3}, {%4,%5,%6,%7}, {%8,%9}, {%0,%1,%2,%3};"
        : "+f"(c[0]), "+f"(c[1]), "+f"(c[2]), "+f"(c[3])
        : "r"(a[0]), "r"(a[1]), "r"(a[2]), "r"(a[3]), "r"(b[0]), "r"(b[1]));
}

__device__ __forceinline__ void cp_async16(void* smem_dst, const void* gmem_src) {
    uint32_t s = (uint32_t)__cvta_generic_to_shared(smem_dst);
    asm volatile("cp.async.ca.shared.global [%0], [%1], 16;\n" :: "r"(s), "l"(gmem_src));
}
__device__ __forceinline__ void cp_async_commit() {
    asm volatile("cp.async.commit_group;\n" ::: "memory");
}
__device__ __forceinline__ void cp_async_wait_all() {
    asm volatile("cp.async.wait_group 0;\n" ::: "memory");
}

#define WS_STRIDE 40      // halves per W row (20 words): conflict-free A frags
#define YS_STRIDE 136     // words per Y pair-row: conflict-free B frags

// per-stage byte offsets inside dynamic smem
#define OFF_WH 0
#define OFF_WL 10240
#define OFF_YH 20480
#define OFF_YL 29184
#define STAGE_BYTES 37888
#define GEMM_SMEM (2 * STAGE_BYTES)     // 75776

__global__ __launch_bounds__(256, 2) void gemm_glu_kernel(
    const float* __restrict__ bias, float* __restrict__ out) {
    extern __shared__ char smraw[];

    const int b  = blockIdx.z;
    const int h0 = blockIdx.y * 64;
    const int l0 = blockIdx.x * 128;
    const int t  = threadIdx.x;
    const int wid  = t >> 5;
    const int lane = t & 31;
    const int wm = wid >> 2;          // 0..1
    const int wn = wid & 3;           // 0..3
    const int g  = lane >> 2;         // 0..7
    const int tq = lane & 3;          // 0..3

    float acc[4][4][4];               // [mfrag: 2a+2g][nfrag][4]
#pragma unroll
    for (int f = 0; f < 4; ++f)
#pragma unroll
        for (int j = 0; j < 4; ++j)
#pragma unroll
            for (int r = 0; r < 4; ++r) acc[f][j][r] = 0.f;

    // loader mappings
    const int wr  = t >> 1;                 // 0..127 tile m-row
    const int seg = t & 1;                  // 0/1 -> 16-half segment
    const int wrow = (wr < 64) ? (h0 + wr) : (HH + h0 + wr - 64);
    const __nv_bfloat16* whp = g_wh + (size_t)wrow * HH + 16 * seg;
    const __nv_bfloat16* wlp = g_wl + (size_t)wrow * HH + 16 * seg;

    const int pr = t >> 4;                  // 0..15 pair-row
    const int lc = (t & 15) * 8;            // 0..120
    const __nv_bfloat16* ybh = g_yh + (size_t)b * HH * LL + (size_t)l0 + lc;
    const __nv_bfloat16* ybl = g_yl + (size_t)b * HH * LL + (size_t)l0 + lc;

    const int m0s[4] = {wm * 32, wm * 32 + 16, 64 + wm * 32, 64 + wm * 32 + 16};

    // ---- W cp.async into a stage
    auto load_w = [&](int k0, char* st) {
        __nv_bfloat16* WhS = (__nv_bfloat16*)(st + OFF_WH) + wr * WS_STRIDE + 16 * seg;
        __nv_bfloat16* WlS = (__nv_bfloat16*)(st + OFF_WL) + wr * WS_STRIDE + 16 * seg;
        cp_async16(WhS,     whp + k0);
        cp_async16(WhS + 8, whp + k0 + 8);
        cp_async16(WlS,     wlp + k0);
        cp_async16(WlS + 8, wlp + k0 + 8);
        cp_async_commit();
    };
    // ---- Y perm + STS into a stage (from staged regs)
    auto store_y = [&](char* st, uint4 e, uint4 o, uint4 el, uint4 ol) {
        uint32_t* Yh = (uint32_t*)(st + OFF_YH) + pr * YS_STRIDE + lc;
        uint32_t* Yl = (uint32_t*)(st + OFF_YL) + pr * YS_STRIDE + lc;
        *(uint4*)Yh = make_uint4(
            __byte_perm(e.x, o.x, 0x5410), __byte_perm(e.x, o.x, 0x7632),
            __byte_perm(e.y, o.y, 0x5410), __byte_perm(e.y, o.y, 0x7632));
        *(uint4*)(Yh + 4) = make_uint4(
            __byte_perm(e.z, o.z, 0x5410), __byte_perm(e.z, o.z, 0x7632),
            __byte_perm(e.w, o.w, 0x5410), __byte_perm(e.w, o.w, 0x7632));
        *(uint4*)Yl = make_uint4(
            __byte_perm(el.x, ol.x, 0x5410), __byte_perm(el.x, ol.x, 0x7632),
            __byte_perm(el.y, ol.y, 0x5410), __byte_perm(el.y, ol.y, 0x7632));
        *(uint4*)(Yl + 4) = make_uint4(
            __byte_perm(el.z, ol.z, 0x5410), __byte_perm(el.z, ol.z, 0x7632),
            __byte_perm(el.w, ol.w, 0x5410), __byte_perm(el.w, ol.w, 0x7632));
    };

    // ---- prologue: fill stage 0 with k0 = 0
    {
        load_w(0, smraw);
        uint4 e  = *(const uint4*)(ybh + (size_t)(2 * pr) * LL);
        uint4 o  = *(const uint4*)(ybh + (size_t)(2 * pr + 1) * LL);
        uint4 el = *(const uint4*)(ybl + (size_t)(2 * pr) * LL);
        uint4 ol = *(const uint4*)(ybl + (size_t)(2 * pr + 1) * LL);
        store_y(smraw, e, o, el, ol);
        cp_async_wait_all();
    }
    __syncthreads();

    int st = 0;
#pragma unroll 1
    for (int k0 = 0; k0 < HH; k0 += 32) {
        char* cur = smraw + st * STAGE_BYTES;
        char* nxt = smraw + (st ^ 1) * STAGE_BYTES;
        const int knext = k0 + 32;
        uint4 e, o, el, ol;
        if (knext < HH) {
            load_w(knext, nxt);                               // async
            const size_t re = (size_t)(knext + 2 * pr) * LL;  // prefetch Y
            e  = *(const uint4*)(ybh + re);
            o  = *(const uint4*)(ybh + re + LL);
            el = *(const uint4*)(ybl + re);
            ol = *(const uint4*)(ybl + re + LL);
        }

        // ---- compute on current stage
        const uint32_t* WhW = (const uint32_t*)(cur + OFF_WH);
        const uint32_t* WlW = (const uint32_t*)(cur + OFF_WL);
        const uint32_t* YhW = (const uint32_t*)(cur + OFF_YH);
        const uint32_t* YlW = (const uint32_t*)(cur + OFF_YL);
#pragma unroll
        for (int ks = 0; ks < 2; ++ks) {
            const int wcol = ks * 8 + tq;
            const int prb  = ks * 8 + tq;
            uint32_t AH[4][4], AL[4][4], BH[4][2], BL[4][2];
#pragma unroll
            for (int f = 0; f < 4; ++f) {
                int r0 = (m0s[f] + g) * (WS_STRIDE / 2) + wcol;
                int r1 = (m0s[f] + g + 8) * (WS_STRIDE / 2) + wcol;
                AH[f][0] = WhW[r0];     AH[f][1] = WhW[r1];
                AH[f][2] = WhW[r0 + 4]; AH[f][3] = WhW[r1 + 4];
                AL[f][0] = WlW[r0];     AL[f][1] = WlW[r1];
                AL[f][2] = WlW[r0 + 4]; AL[f][3] = WlW[r1 + 4];
            }
#pragma unroll
            for (int j = 0; j < 4; ++j) {
                int n = wn * 32 + j * 8 + g;
                BH[j][0] = YhW[prb * YS_STRIDE + n];
                BH[j][1] = YhW[(prb + 4) * YS_STRIDE + n];
                BL[j][0] = YlW[prb * YS_STRIDE + n];
                BL[j][1] = YlW[(prb + 4) * YS_STRIDE + n];
            }
#pragma unroll
            for (int f = 0; f < 4; ++f)
#pragma unroll
                for (int j = 0; j < 4; ++j) {
                    mma_bf16(acc[f][j], AH[f], BH[j]);
                    mma_bf16(acc[f][j], AH[f], BL[j]);
                    mma_bf16(acc[f][j], AL[f], BH[j]);
                }
        }

        if (knext < HH) store_y(nxt, e, o, el, ol);
        cp_async_wait_all();
        __syncthreads();
        st ^= 1;
    }

    // Epilogue: GLU.  a-frag f pairs with g-frag f+2 (same rows).
#pragma unroll
    for (int ai = 0; ai < 2; ++ai) {
        const int hrow0 = h0 + wm * 32 + ai * 16 + g;     // rows (c0,c1)
        const int hrow8 = hrow0 + 8;                       // rows (c2,c3)
        const float ba0 = bias[hrow0],      ba8 = bias[hrow8];
        const float bg0 = bias[HH + hrow0], bg8 = bias[HH + hrow8];
        float* o0 = out + ((size_t)b * HH + hrow0) * LL + l0 + wn * 32;
        float* o8 = out + ((size_t)b * HH + hrow8) * LL + l0 + wn * 32;
#pragma unroll
        for (int j = 0; j < 4; ++j) {
            const int cc = j * 8 + 2 * tq;
            float za0 = acc[ai][j][0] + ba0, za1 = acc[ai][j][1] + ba0;
            float zg0 = acc[ai + 2][j][0] + bg0, zg1 = acc[ai + 2][j][1] + bg0;
            float za2 = acc[ai][j][2] + ba8, za3 = acc[ai][j][3] + ba8;
            float zg2 = acc[ai + 2][j][2] + bg8, zg3 = acc[ai + 2][j][3] + bg8;
            *(float2*)(o0 + cc) = make_float2(za0 / (1.0f + __expf(-zg0)),
                                              za1 / (1.0f + __expf(-zg1)));
            *(float2*)(o8 + cc) = make_float2(za2 / (1.0f + __expf(-zg2)),
                                              za3 / (1.0f + __expf(-zg3)));
        }
    }
}

// ---------------------------------------------------------------------------
extern "C" void kernel_launch(void* const* d_in, const int* in_sizes, int n_in,
                              void* d_out, int out_size) {
    const float* u  = (const float*)d_in[0];   // (B, H, L)
    const float* k  = (const float*)d_in[1];   // (1, H, L)
    const float* D  = (const float*)d_in[2];   // (1, H)
    const float* W  = (const float*)d_in[3];   // (2H, H)
    const float* bv = (const float*)d_in[4];   // (2H,)
    float* out = (float*)d_out;

    const int smem_fft = (N2 * 2 + 2048) * sizeof(float2);   // 80 KB
    cudaFuncSetAttribute(kf_kernel,   cudaFuncAttributeMaxDynamicSharedMemorySize, smem_fft);
    cudaFuncSetAttribute(conv_kernel, cudaFuncAttributeMaxDynamicSharedMemorySize, smem_fft);
    cudaFuncSetAttribute(gemm_glu_kernel, cudaFuncAttributeMaxDynamicSharedMemorySize, GEMM_SMEM);

    kf_kernel<<<HH, 512, smem_fft>>>(k);
    wsplit_kernel<<<2 * HH, 256>>>(W);
    conv_kernel<<<BB * HH, 512, smem_fft>>>(u, D);
    gemm_glu_kernel<<<dim3(LL / 128, HH / 64, BB), 256, GEMM_SMEM>>>(bv, out);
}

// round 11
// speedup vs baseline: 1.1814x; 1.1814x over previous
#include <cuda_runtime.h>
#include <cuda_bf16.h>
#include <cstdint>

// Problem constants
#define BB 8
#define HH 768
#define LL 4096
#define N2 4096          // complex FFT size (= N/2, N = 8192)
#define LOGN2 12
#define KF_STRIDE 4100   // 4097 used, padded

#define PI_F 3.14159265358979323846f

// Scratch (device globals: allocation APIs are forbidden)
__device__ __nv_bfloat16 g_yh[(size_t)BB * HH * LL];   // gelu(y) hi, ~50 MB
__device__ __nv_bfloat16 g_yl[(size_t)BB * HH * LL];   // gelu(y) lo, ~50 MB
__device__ __nv_bfloat16 g_wh[(size_t)2 * HH * HH];    // W hi
__device__ __nv_bfloat16 g_wl[(size_t)2 * HH * HH];    // W lo
__device__ float2 g_kf[(size_t)HH * KF_STRIDE];        // kernel spectrum, ~25 MB

// ---------------------------------------------------------------------------
// complex helpers
__device__ __forceinline__ float2 cmul(float2 a, float2 b) {
    return make_float2(a.x * b.x - a.y * b.y, a.x * b.y + a.y * b.x);
}
__device__ __forceinline__ float2 cmulc(float2 a, float2 b) {  // a * conj(b)
    return make_float2(a.x * b.x + a.y * b.y, a.y * b.x - a.x * b.y);
}

__device__ __forceinline__ float gelu_exact(float x) {
    return 0.5f * x * (1.0f + erff(x * 0.70710678118654752f));
}

// ---------------------------------------------------------------------------
// Stockham radix-2 FFT of 4096 complex points in shared memory.
template <bool INV>
__device__ void fft4096(float2* bufA, float2* bufB, const float2* tw, int tid) {
    float2* src = bufA;
    float2* dst = bufB;
#pragma unroll 1
    for (int stage = 0; stage < LOGN2; ++stage) {
        __syncthreads();
        const int s = 1 << stage;
#pragma unroll
        for (int it = 0; it < 4; ++it) {
            int i = tid + it * 512;          // 0..2047  (i = p*s + q)
            int p = i >> stage;
            int q = i & (s - 1);
            float2 w = tw[p << stage];
            if (INV) w.y = -w.y;
            float2 a  = src[i];
            float2 b  = src[i + 2048];
            float2 sum = make_float2(a.x + b.x, a.y + b.y);
            float2 dif = make_float2(a.x - b.x, a.y - b.y);
            int od = q + s * 2 * p;
            dst[od]     = sum;
            dst[od + s] = cmul(dif, w);
        }
        float2* t = src; src = dst; dst = t;
    }
    __syncthreads();
}

__device__ __forceinline__ void build_twiddles(float2* tw, int tid) {
    for (int i = tid; i < 2048; i += 512) {
        float s, c;
        __sincosf(-(2.0f * PI_F / (float)N2) * (float)i, &s, &c);
        tw[i] = make_float2(c, s);
    }
}

// ---------------------------------------------------------------------------
// Kernel 1: spectrum of conv kernel k (768 rows).
__global__ void kf_kernel(const float* __restrict__ kin) {
    extern __shared__ float2 sm[];
    float2* A  = sm;
    float2* Bb = sm + N2;
    float2* tw = sm + 2 * N2;
    const int h   = blockIdx.x;
    const int tid = threadIdx.x;

    build_twiddles(tw, tid);

    const float2* kr = (const float2*)(kin + (size_t)h * LL);
#pragma unroll
    for (int it = 0; it < 4; ++it) {
        int n = tid + it * 512;
        A[n] = kr[n];
    }
#pragma unroll
    for (int it = 4; it < 8; ++it) {
        int n = tid + it * 512;
        A[n] = make_float2(0.f, 0.f);
    }

    fft4096<false>(A, Bb, tw, tid);

    float2* kf = g_kf + (size_t)h * KF_STRIDE;
    for (int k = tid; k <= 2048; k += 512) {
        if (k == 0) {
            float2 Z0 = A[0];
            kf[0]    = make_float2(Z0.x + Z0.y, 0.f);
            kf[4096] = make_float2(Z0.x - Z0.y, 0.f);
        } else if (k == 2048) {
            float2 Z = A[2048];
            kf[2048] = make_float2(Z.x, -Z.y);
        } else {
            int kp = N2 - k;
            float2 Zk = A[k], Zp = A[kp];
            float2 Fe = make_float2(0.5f * (Zk.x + Zp.x), 0.5f * (Zk.y - Zp.y));
            float2 Fo = make_float2(0.5f * (Zk.y + Zp.y), 0.5f * (Zp.x - Zk.x));
            float sw, cw;
            __sincosf(-(2.0f * PI_F / 8192.0f) * (float)k, &sw, &cw);
            float2 W = make_float2(cw, sw);
            float2 t = cmul(Fo, W);
            kf[k]  = make_float2(Fe.x + t.x, Fe.y + t.y);
            kf[kp] = make_float2(Fe.x - t.x, -(Fe.y - t.y));
        }
    }
}

// ---------------------------------------------------------------------------
// Kernel 2: per (b,h) row — rfft(u) * Kf -> irfft -> + D*u -> gelu -> split bf16
__global__ void conv_kernel(const float* __restrict__ u, const float* __restrict__ D) {
    extern __shared__ float2 sm[];
    float2* A  = sm;
    float2* Bb = sm + N2;
    float2* tw = sm + 2 * N2;
    const int row = blockIdx.x;          // b*HH + h
    const int tid = threadIdx.x;
    const int hh  = row % HH;

    build_twiddles(tw, tid);

    const float2* u2 = (const float2*)(u + (size_t)row * LL);
    float2 ureg[4];
#pragma unroll
    for (int it = 0; it < 4; ++it) {
        int n = tid + it * 512;
        float2 v = u2[n];
        ureg[it] = v;
        A[n] = v;
    }
#pragma unroll
    for (int it = 4; it < 8; ++it) {
        int n = tid + it * 512;
        A[n] = make_float2(0.f, 0.f);
    }

    fft4096<false>(A, Bb, tw, tid);   // Z in A

    const float2* kf = g_kf + (size_t)hh * KF_STRIDE;
    for (int k = tid; k <= 2048; k += 512) {
        if (k == 0) {
            float2 Z0 = A[0];
            float X0 = Z0.x + Z0.y;
            float X1 = Z0.x - Z0.y;
            float2 K0 = kf[0], K1 = kf[4096];
            float2 Y0 = make_float2(X0 * K0.x, X0 * K0.y);
            float2 Y1 = make_float2(X1 * K1.x, X1 * K1.y);
            float2 Ge = make_float2(0.5f * (Y0.x + Y1.x), 0.5f * (Y0.y - Y1.y));
            float2 Go = make_float2(0.5f * (Y0.x - Y1.x), 0.5f * (Y0.y + Y1.y));
            A[0] = make_float2(Ge.x - Go.y, Ge.y + Go.x);
        } else if (k == 2048) {
            float2 Z = A[2048];
            float2 X = make_float2(Z.x, -Z.y);
            float2 Y = cmul(X, kf[2048]);
            A[2048] = make_float2(Y.x, -Y.y);
        } else {
            int kp = N2 - k;
            float2 Zk = A[k], Zp = A[kp];
            float2 Fe = make_float2(0.5f * (Zk.x + Zp.x), 0.5f * (Zk.y - Zp.y));
            float2 Fo = make_float2(0.5f * (Zk.y + Zp.y), 0.5f * (Zp.x - Zk.x));
            float sw, cw;
            __sincosf(-(2.0f * PI_F / 8192.0f) * (float)k, &sw, &cw);
            float2 W = make_float2(cw, sw);
            float2 t = cmul(Fo, W);
            float2 Xk = make_float2(Fe.x + t.x, Fe.y + t.y);
            float2 Xp = make_float2(Fe.x - t.x, -(Fe.y - t.y));
            float2 Ya = cmul(Xk, kf[k]);
            float2 Yb = cmul(Xp, kf[kp]);
            float2 Ge = make_float2(0.5f * (Ya.x + Yb.x), 0.5f * (Ya.y - Yb.y));
            float2 Am = make_float2(0.5f * (Ya.x - Yb.x), 0.5f * (Ya.y + Yb.y));
            float2 Go = cmulc(Am, W);
            A[k]  = make_float2(Ge.x - Go.y, Ge.y + Go.x);
            A[kp] = make_float2(Ge.x + Go.y, Go.x - Ge.y);
        }
    }

    fft4096<true>(A, Bb, tw, tid);    // z2 in A (unscaled inverse)

    const float Dh  = D[hh];
    const float inv = 1.0f / (float)N2;
    __nv_bfloat16* yh = g_yh + (size_t)row * LL;
    __nv_bfloat16* yl = g_yl + (size_t)row * LL;
#pragma unroll
    for (int it = 0; it < 4; ++it) {
        int n = tid + it * 512;
        float2 z = A[n];
        float y0 = gelu_exact(z.x * inv + Dh * ureg[it].x);
        float y1 = gelu_exact(z.y * inv + Dh * ureg[it].y);
        __nv_bfloat16 h0 = __float2bfloat16(y0);
        __nv_bfloat16 h1 = __float2bfloat16(y1);
        __nv_bfloat16 l0 = __float2bfloat16(y0 - __bfloat162float(h0));
        __nv_bfloat16 l1 = __float2bfloat16(y1 - __bfloat162float(h1));
        __nv_bfloat162 hv; hv.x = h0; hv.y = h1;
        __nv_bfloat162 lv; lv.x = l0; lv.y = l1;
        *(__nv_bfloat162*)(yh + 2 * n) = hv;
        *(__nv_bfloat162*)(yl + 2 * n) = lv;
    }
}

// ---------------------------------------------------------------------------
// Kernel 2b: split W (2H x H fp32) into bf16 hi/lo
__global__ void wsplit_kernel(const float* __restrict__ W) {
    int r = blockIdx.x;
    for (int c = threadIdx.x; c < HH; c += 256) {
        float w = W[(size_t)r * HH + c];
        __nv_bfloat16 hi = __float2bfloat16(w);
        __nv_bfloat16 lo = __float2bfloat16(w - __bfloat162float(hi));
        g_wh[(size_t)r * HH + c] = hi;
        g_wl[(size_t)r * HH + c] = lo;
    }
}

// ---------------------------------------------------------------------------
// Kernel 3: tensor-core GEMM with split-bf16, ldmatrix fragments (R10).
// Y smem is raw k-major [32][YS_HSTRIDE]; B frags via ldmatrix.x4.trans.
// W smem [128][WS_STRIDE]; A frags via ldmatrix.x4. All loads cp.async,
// 2-stage pipeline, one __syncthreads per K-chunk.
__device__ __forceinline__ void mma_bf16(float* c, const uint32_t* a, const uint32_t* b) {
    asm volatile(
        "mma.sync.aligned.m16n8k16.row.col.f32.bf16.bf16.f32 "
        "{%0,%1,%2,%3}, {%4,%5,%6,%7}, {%8,%9}, {%0,%1,%2,%3};"
        : "+f"(c[0]), "+f"(c[1]), "+f"(c[2]), "+f"(c[3])
        : "r"(a[0]), "r"(a[1]), "r"(a[2]), "r"(a[3]), "r"(b[0]), "r"(b[1]));
}

__device__ __forceinline__ void cp_async16(void* smem_dst, const void* gmem_src) {
    uint32_t s = (uint32_t)__cvta_generic_to_shared(smem_dst);
    asm volatile("cp.async.ca.shared.global [%0], [%1], 16;\n" :: "r"(s), "l"(gmem_src));
}
__device__ __forceinline__ void cp_async_commit() {
    asm volatile("cp.async.commit_group;\n" ::: "memory");
}
__device__ __forceinline__ void cp_async_wait_all() {
    asm volatile("cp.async.wait_group 0;\n" ::: "memory");
}
__device__ __forceinline__ void ldsm_x4(uint32_t* r, uint32_t saddr) {
    asm volatile("ldmatrix.sync.aligned.m8n8.x4.shared.b16 {%0,%1,%2,%3}, [%4];"
        : "=r"(r[0]), "=r"(r[1]), "=r"(r[2]), "=r"(r[3]) : "r"(saddr));
}
__device__ __forceinline__ void ldsm_x4_t(uint32_t* r, uint32_t saddr) {
    asm volatile("ldmatrix.sync.aligned.m8n8.x4.trans.shared.b16 {%0,%1,%2,%3}, [%4];"
        : "=r"(r[0]), "=r"(r[1]), "=r"(r[2]), "=r"(r[3]) : "r"(saddr));
}

#define WS_STRIDE 40       // halves per W row (80 B): LDSM conflict-free
#define YS_HSTRIDE 136     // halves per Y k-row (272 B): LDSM.trans conflict-free

// per-stage byte offsets in dynamic smem
#define OFF_WH 0
#define OFF_WL 10240
#define OFF_YH 20480
#define OFF_YL 29184
#define STAGE_BYTES 37888
#define GEMM_SMEM (2 * STAGE_BYTES)     // 75776

__global__ __launch_bounds__(256, 2) void gemm_glu_kernel(
    const float* __restrict__ bias, float* __restrict__ out) {
    extern __shared__ char smraw[];

    const int b  = blockIdx.z;
    const int h0 = blockIdx.y * 64;
    const int l0 = blockIdx.x * 128;
    const int t  = threadIdx.x;
    const int wid  = t >> 5;
    const int lane = t & 31;
    const int wm = wid >> 2;          // 0..1
    const int wn = wid & 3;           // 0..3
    const int g  = lane >> 2;         // 0..7
    const int tq = lane & 3;          // 0..3

    float acc[4][4][4];               // [mfrag: 2a+2g][nfrag][4]
#pragma unroll
    for (int f = 0; f < 4; ++f)
#pragma unroll
        for (int j = 0; j < 4; ++j)
#pragma unroll
            for (int r = 0; r < 4; ++r) acc[f][j][r] = 0.f;

    // ---- loader mappings
    const int wr  = t >> 1;                 // 0..127 W tile m-row
    const int seg = t & 1;                  // 16-half segment
    const int wrow = (wr < 64) ? (h0 + wr) : (HH + h0 + wr - 64);
    const __nv_bfloat16* whp = g_wh + (size_t)wrow * HH + 16 * seg;
    const __nv_bfloat16* wlp = g_wl + (size_t)wrow * HH + 16 * seg;

    const int yr = t >> 3;                  // 0..31 Y k-row
    const int yc = (t & 7) * 16;            // half col 0..112
    const __nv_bfloat16* ybh = g_yh + (size_t)b * HH * LL + (size_t)l0 + yc;
    const __nv_bfloat16* ybl = g_yl + (size_t)b * HH * LL + (size_t)l0 + yc;

    const int m0s[4] = {wm * 32, wm * 32 + 16, 64 + wm * 32, 64 + wm * 32 + 16};

    // ldmatrix per-lane byte offsets (within a stage)
    const int lrow8 = (lane & 7) + ((lane >> 3) & 1) * 8;   // row within 16
    const int lhalf = lane >> 4;                            // 0..1 second pair
    const int aoff = lrow8 * (WS_STRIDE * 2) + lhalf * 16;  // + m0*80 + ks*32
    const int boff = lrow8 * (YS_HSTRIDE * 2)
                   + (wn * 32 + lhalf * 8) * 2;             // + ks*16*272 + jp*32

    auto load_stage = [&](int k0, char* st) {
        __nv_bfloat16* WhS = (__nv_bfloat16*)(st + OFF_WH) + wr * WS_STRIDE + 16 * seg;
        __nv_bfloat16* WlS = (__nv_bfloat16*)(st + OFF_WL) + wr * WS_STRIDE + 16 * seg;
        cp_async16(WhS,     whp + k0);
        cp_async16(WhS + 8, whp + k0 + 8);
        cp_async16(WlS,     wlp + k0);
        cp_async16(WlS + 8, wlp + k0 + 8);
        __nv_bfloat16* YhS = (__nv_bfloat16*)(st + OFF_YH) + yr * YS_HSTRIDE + yc;
        __nv_bfloat16* YlS = (__nv_bfloat16*)(st + OFF_YL) + yr * YS_HSTRIDE + yc;
        const size_t ro = (size_t)(k0 + yr) * LL;
        cp_async16(YhS,     ybh + ro);
        cp_async16(YhS + 8, ybh + ro + 8);
        cp_async16(YlS,     ybl + ro);
        cp_async16(YlS + 8, ybl + ro + 8);
        cp_async_commit();
    };

    // ---- prologue
    load_stage(0, smraw);
    cp_async_wait_all();
    __syncthreads();

    int st = 0;
#pragma unroll 1
    for (int k0 = 0; k0 < HH; k0 += 32) {
        char* cur = smraw + st * STAGE_BYTES;
        char* nxt = smraw + (st ^ 1) * STAGE_BYTES;
        const int knext = k0 + 32;
        if (knext < HH) load_stage(knext, nxt);

        const uint32_t whb = (uint32_t)__cvta_generic_to_shared(cur + OFF_WH) + aoff;
        const uint32_t wlb = (uint32_t)__cvta_generic_to_shared(cur + OFF_WL) + aoff;
        const uint32_t yhb = (uint32_t)__cvta_generic_to_shared(cur + OFF_YH) + boff;
        const uint32_t ylb = (uint32_t)__cvta_generic_to_shared(cur + OFF_YL) + boff;

#pragma unroll
        for (int ks = 0; ks < 2; ++ks) {
            uint32_t AH[4][4], AL[4][4], BH[4][2], BL[4][2];
#pragma unroll
            for (int f = 0; f < 4; ++f) {
                ldsm_x4(AH[f], whb + m0s[f] * (WS_STRIDE * 2) + ks * 32);
                ldsm_x4(AL[f], wlb + m0s[f] * (WS_STRIDE * 2) + ks * 32);
            }
#pragma unroll
            for (int jp = 0; jp < 2; ++jp) {
                ldsm_x4_t(&BH[2 * jp][0], yhb + ks * 16 * (YS_HSTRIDE * 2) + jp * 32);
                ldsm_x4_t(&BL[2 * jp][0], ylb + ks * 16 * (YS_HSTRIDE * 2) + jp * 32);
            }
#pragma unroll
            for (int f = 0; f < 4; ++f)
#pragma unroll
                for (int j = 0; j < 4; ++j) {
                    mma_bf16(acc[f][j], AH[f], BH[j]);
                    mma_bf16(acc[f][j], AH[f], BL[j]);
                    mma_bf16(acc[f][j], AL[f], BH[j]);
                }
        }

        cp_async_wait_all();
        __syncthreads();
        st ^= 1;
    }

    // Epilogue: GLU.  a-frag f pairs with g-frag f+2 (same rows).
#pragma unroll
    for (int ai = 0; ai < 2; ++ai) {
        const int hrow0 = h0 + wm * 32 + ai * 16 + g;     // rows (c0,c1)
        const int hrow8 = hrow0 + 8;                       // rows (c2,c3)
        const float ba0 = bias[hrow0],      ba8 = bias[hrow8];
        const float bg0 = bias[HH + hrow0], bg8 = bias[HH + hrow8];
        float* o0 = out + ((size_t)b * HH + hrow0) * LL + l0 + wn * 32;
        float* o8 = out + ((size_t)b * HH + hrow8) * LL + l0 + wn * 32;
#pragma unroll
        for (int j = 0; j < 4; ++j) {
            const int cc = j * 8 + 2 * tq;
            float za0 = acc[ai][j][0] + ba0, za1 = acc[ai][j][1] + ba0;
            float zg0 = acc[ai + 2][j][0] + bg0, zg1 = acc[ai + 2][j][1] + bg0;
            float za2 = acc[ai][j][2] + ba8, za3 = acc[ai][j][3] + ba8;
            float zg2 = acc[ai + 2][j][2] + bg8, zg3 = acc[ai + 2][j][3] + bg8;
            *(float2*)(o0 + cc) = make_float2(za0 / (1.0f + __expf(-zg0)),
                                              za1 / (1.0f + __expf(-zg1)));
            *(float2*)(o8 + cc) = make_float2(za2 / (1.0f + __expf(-zg2)),
                                              za3 / (1.0f + __expf(-zg3)));
        }
    }
}

// ---------------------------------------------------------------------------
extern "C" void kernel_launch(void* const* d_in, const int* in_sizes, int n_in,
                              void* d_out, int out_size) {
    const float* u  = (const float*)d_in[0];   // (B, H, L)
    const float* k  = (const float*)d_in[1];   // (1, H, L)
    const float* D  = (const float*)d_in[2];   // (1, H)
    const float* W  = (const float*)d_in[3];   // (2H, H)
    const float* bv = (const float*)d_in[4];   // (2H,)
    float* out = (float*)d_out;

    const int smem_fft = (N2 * 2 + 2048) * sizeof(float2);   // 80 KB
    cudaFuncSetAttribute(kf_kernel,   cudaFuncAttributeMaxDynamicSharedMemorySize, smem_fft);
    cudaFuncSetAttribute(conv_kernel, cudaFuncAttributeMaxDynamicSharedMemorySize, smem_fft);
    cudaFuncSetAttribute(gemm_glu_kernel, cudaFuncAttributeMaxDynamicSharedMemorySize, GEMM_SMEM);

    kf_kernel<<<HH, 512, smem_fft>>>(k);
    wsplit_kernel<<<2 * HH, 256>>>(W);
    conv_kernel<<<BB * HH, 512, smem_fft>>>(u, D);
    gemm_glu_kernel<<<dim3(LL / 128, HH / 64, BB), 256, GEMM_SMEM>>>(bv, out);
}